// round 1
// baseline (speedup 1.0000x reference)
#include <cuda_runtime.h>

// Problem dims (fixed per reference)
#define TSEQ 4096
#define CIN  2048
#define NF   2048
#define QKVN 6144            // 3*NF
#define NEGV -1e30f

// Tiling
#define BM 128
#define BN 128
#define BK 8
#define TM 8
#define TN 8

// Scratch (device globals — no allocation allowed)
__device__ float g_qkv[(size_t)TSEQ * QKVN];   // 96 MB: [T, 3*NF]  (q | k | v)
__device__ float g_att[(size_t)TSEQ * TSEQ];   // 64 MB: attention matrix / probs

// ---------------------------------------------------------------------------
// Kernel 1: qkv = x @ W + b      (4096x2048) @ (2048x6144)
// ---------------------------------------------------------------------------
__global__ __launch_bounds__(256, 1) void k_qkv(const float* __restrict__ X,
                                                const float* __restrict__ W,
                                                const float* __restrict__ bias) {
    __shared__ float As[BK][BM];
    __shared__ float Bs[BK][BN];
    const int bx = blockIdx.x, by = blockIdx.y;
    const int tid = threadIdx.x;
    const int tc = tid & 15;        // BN/TN = 16
    const int tr = tid >> 4;        // BM/TM = 16
    const int aRow = tid >> 1;      // 0..127
    const int aCol = (tid & 1) << 2;
    const int bRow = tid >> 5;      // 0..7
    const int bCol = (tid & 31) << 2;
    const float* Ab = X + (size_t)by * BM * CIN;
    const float* Bb = W + (size_t)bx * BN;
    float acc[TM][TN] = {};
    for (int k0 = 0; k0 < CIN; k0 += BK) {
        float4 a4 = *(const float4*)(Ab + (size_t)aRow * CIN + k0 + aCol);
        As[aCol + 0][aRow] = a4.x;
        As[aCol + 1][aRow] = a4.y;
        As[aCol + 2][aRow] = a4.z;
        As[aCol + 3][aRow] = a4.w;
        *(float4*)(&Bs[bRow][bCol]) =
            *(const float4*)(Bb + (size_t)(k0 + bRow) * QKVN + bCol);
        __syncthreads();
#pragma unroll
        for (int k = 0; k < BK; k++) {
            float rm[TM], rn[TN];
#pragma unroll
            for (int m = 0; m < TM; m++) rm[m] = As[k][tr * TM + m];
#pragma unroll
            for (int n = 0; n < TN; n++) rn[n] = Bs[k][tc * TN + n];
#pragma unroll
            for (int m = 0; m < TM; m++)
#pragma unroll
                for (int n = 0; n < TN; n++)
                    acc[m][n] = fmaf(rm[m], rn[n], acc[m][n]);
        }
        __syncthreads();
    }
#pragma unroll
    for (int m = 0; m < TM; m++) {
        const int row = by * BM + tr * TM + m;
#pragma unroll
        for (int n = 0; n < TN; n += 4) {
            const int col = bx * BN + tc * TN + n;
            float4 o;
            o.x = acc[m][n + 0] + bias[col + 0];
            o.y = acc[m][n + 1] + bias[col + 1];
            o.z = acc[m][n + 2] + bias[col + 2];
            o.w = acc[m][n + 3] + bias[col + 3];
            *(float4*)(g_qkv + (size_t)row * QKVN + col) = o;
        }
    }
}

// ---------------------------------------------------------------------------
// Kernel 2: att = mask(q @ k^T * scale)   — skips fully-masked blocks
// q = g_qkv[:, 0:NF], k = g_qkv[:, NF:2NF]  (NT GEMM, K = NF)
// ---------------------------------------------------------------------------
__global__ __launch_bounds__(256, 1) void k_att(const int* __restrict__ npadd_p) {
    __shared__ float As[BK][BM];
    __shared__ float Bs[BK][BN];
    const int n_padd = *npadd_p;
    const int bx = blockIdx.x, by = blockIdx.y;   // bx: key cols, by: query rows
    const int tid = threadIdx.x;
    const int rowMax = by * BM + BM - 1;
    const int colMin = bx * BN;
    const int colMax = colMin + BN - 1;

    if (colMin > rowMax || rowMax < n_padd || colMax < n_padd) {
        // fully masked block: write NEG, no compute
        const float4 negv = make_float4(NEGV, NEGV, NEGV, NEGV);
        for (int i = tid; i < BM * BN / 4; i += 256) {
            int m = i / (BN / 4);
            int n = (i % (BN / 4)) * 4;
            *(float4*)(g_att + (size_t)(by * BM + m) * TSEQ + colMin + n) = negv;
        }
        return;
    }

    const int tc = tid & 15;
    const int tr = tid >> 4;
    const int aRow = tid >> 1;
    const int aCol = (tid & 1) << 2;
    const float* Ab = g_qkv + (size_t)by * BM * QKVN;        // q rows
    const float* Kb = g_qkv + (size_t)bx * BN * QKVN + NF;   // k rows
    float acc[TM][TN] = {};
    for (int k0 = 0; k0 < NF; k0 += BK) {
        float4 a4 = *(const float4*)(Ab + (size_t)aRow * QKVN + k0 + aCol);
        As[aCol + 0][aRow] = a4.x;
        As[aCol + 1][aRow] = a4.y;
        As[aCol + 2][aRow] = a4.z;
        As[aCol + 3][aRow] = a4.w;
        float4 b4 = *(const float4*)(Kb + (size_t)aRow * QKVN + k0 + aCol);
        Bs[aCol + 0][aRow] = b4.x;
        Bs[aCol + 1][aRow] = b4.y;
        Bs[aCol + 2][aRow] = b4.z;
        Bs[aCol + 3][aRow] = b4.w;
        __syncthreads();
#pragma unroll
        for (int k = 0; k < BK; k++) {
            float rm[TM], rn[TN];
#pragma unroll
            for (int m = 0; m < TM; m++) rm[m] = As[k][tr * TM + m];
#pragma unroll
            for (int n = 0; n < TN; n++) rn[n] = Bs[k][tc * TN + n];
#pragma unroll
            for (int m = 0; m < TM; m++)
#pragma unroll
                for (int n = 0; n < TN; n++)
                    acc[m][n] = fmaf(rm[m], rn[n], acc[m][n]);
        }
        __syncthreads();
    }
    const float scale = rsqrtf((float)NF);
#pragma unroll
    for (int m = 0; m < TM; m++) {
        const int row = by * BM + tr * TM + m;
#pragma unroll
        for (int n = 0; n < TN; n += 4) {
            const int col = bx * BN + tc * TN + n;
            float4 o;
            o.x = (col + 0 <= row && col + 0 >= n_padd && row >= n_padd) ? acc[m][n + 0] * scale : NEGV;
            o.y = (col + 1 <= row && col + 1 >= n_padd && row >= n_padd) ? acc[m][n + 1] * scale : NEGV;
            o.z = (col + 2 <= row && col + 2 >= n_padd && row >= n_padd) ? acc[m][n + 2] * scale : NEGV;
            o.w = (col + 3 <= row && col + 3 >= n_padd && row >= n_padd) ? acc[m][n + 3] * scale : NEGV;
            *(float4*)(g_att + (size_t)row * TSEQ + col) = o;
        }
    }
}

// ---------------------------------------------------------------------------
// Kernel 3: row softmax in place (padding rows -> 0)
// ---------------------------------------------------------------------------
__global__ __launch_bounds__(256) void k_softmax(const int* __restrict__ npadd_p) {
    const int r = blockIdx.x;
    const int n_padd = *npadd_p;
    float* row = g_att + (size_t)r * TSEQ;
    const int tid = threadIdx.x;
    if (r < n_padd) {
        const float4 z = make_float4(0.f, 0.f, 0.f, 0.f);
        for (int c = tid * 4; c < TSEQ; c += 256 * 4) *(float4*)(row + c) = z;
        return;
    }
    __shared__ float redmax[8];
    __shared__ float redsum[8];
    float vals[TSEQ / 256];
    float mx = NEGV;
#pragma unroll
    for (int i = 0; i < TSEQ / 256; i++) {
        vals[i] = row[tid + i * 256];
        mx = fmaxf(mx, vals[i]);
    }
#pragma unroll
    for (int o = 16; o > 0; o >>= 1) mx = fmaxf(mx, __shfl_xor_sync(0xffffffffu, mx, o));
    if ((tid & 31) == 0) redmax[tid >> 5] = mx;
    __syncthreads();
    mx = redmax[0];
#pragma unroll
    for (int i = 1; i < 8; i++) mx = fmaxf(mx, redmax[i]);

    float s = 0.f;
#pragma unroll
    for (int i = 0; i < TSEQ / 256; i++) {
        vals[i] = expf(vals[i] - mx);
        s += vals[i];
    }
#pragma unroll
    for (int o = 16; o > 0; o >>= 1) s += __shfl_xor_sync(0xffffffffu, s, o);
    if ((tid & 31) == 0) redsum[tid >> 5] = s;
    __syncthreads();
    s = redsum[0];
#pragma unroll
    for (int i = 1; i < 8; i++) s += redsum[i];
    const float inv = 1.f / s;
#pragma unroll
    for (int i = 0; i < TSEQ / 256; i++) row[tid + i * 256] = vals[i] * inv;
}

// ---------------------------------------------------------------------------
// Kernel 4: y = p @ v   (K-loop capped at causal limit per row-block)
// v = g_qkv[:, 2NF:3NF]
// ---------------------------------------------------------------------------
__global__ __launch_bounds__(256, 1) void k_out(float* __restrict__ Y) {
    __shared__ float As[BK][BM];
    __shared__ float Bs[BK][BN];
    const int bx = blockIdx.x, by = blockIdx.y;
    const int tid = threadIdx.x;
    const int tc = tid & 15;
    const int tr = tid >> 4;
    const int aRow = tid >> 1;
    const int aCol = (tid & 1) << 2;
    const int bRow = tid >> 5;
    const int bCol = (tid & 31) << 2;
    const float* Ab = g_att + (size_t)by * BM * TSEQ;
    const float* Bb = g_qkv + 2 * NF + (size_t)bx * BN;
    const int kMax = (by + 1) * BM;   // p[i][j] == 0 for j > i (causal)
    float acc[TM][TN] = {};
    for (int k0 = 0; k0 < kMax; k0 += BK) {
        float4 a4 = *(const float4*)(Ab + (size_t)aRow * TSEQ + k0 + aCol);
        As[aCol + 0][aRow] = a4.x;
        As[aCol + 1][aRow] = a4.y;
        As[aCol + 2][aRow] = a4.z;
        As[aCol + 3][aRow] = a4.w;
        *(float4*)(&Bs[bRow][bCol]) =
            *(const float4*)(Bb + (size_t)(k0 + bRow) * QKVN + bCol);
        __syncthreads();
#pragma unroll
        for (int k = 0; k < BK; k++) {
            float rm[TM], rn[TN];
#pragma unroll
            for (int m = 0; m < TM; m++) rm[m] = As[k][tr * TM + m];
#pragma unroll
            for (int n = 0; n < TN; n++) rn[n] = Bs[k][tc * TN + n];
#pragma unroll
            for (int m = 0; m < TM; m++)
#pragma unroll
                for (int n = 0; n < TN; n++)
                    acc[m][n] = fmaf(rm[m], rn[n], acc[m][n]);
        }
        __syncthreads();
    }
#pragma unroll
    for (int m = 0; m < TM; m++) {
        const int row = by * BM + tr * TM + m;
#pragma unroll
        for (int n = 0; n < TN; n += 4) {
            const int col = bx * BN + tc * TN + n;
            float4 o;
            o.x = acc[m][n + 0];
            o.y = acc[m][n + 1];
            o.z = acc[m][n + 2];
            o.w = acc[m][n + 3];
            *(float4*)(Y + (size_t)row * NF + col) = o;
        }
    }
}

// ---------------------------------------------------------------------------
extern "C" void kernel_launch(void* const* d_in, const int* in_sizes, int n_in,
                              void* d_out, int out_size) {
    const float* x  = (const float*)d_in[0];
    const float* W  = (const float*)d_in[1];
    const float* b  = (const float*)d_in[2];
    const int* npad = (const int*)d_in[3];
    float* y = (float*)d_out;

    dim3 blk(256);
    k_qkv<<<dim3(QKVN / BN, TSEQ / BM), blk>>>(x, W, b);
    k_att<<<dim3(TSEQ / BN, TSEQ / BM), blk>>>(npad);
    k_softmax<<<TSEQ, blk>>>(npad);
    k_out<<<dim3(NF / BN, TSEQ / BM), blk>>>(y);
}

// round 5
// speedup vs baseline: 2.0385x; 2.0385x over previous
#include <cuda_runtime.h>
#include <cstdint>

// Problem dims (fixed)
#define TSEQ 4096
#define CIN  2048
#define NF   2048
#define QKVN 6144
#define NEGV -1e30f

// GEMM tiling
#define BM 128
#define BN 128
#define BK 32
#define PADK 36                      // smem row stride (floats): conflict-free frag loads
#define TILE_FLOATS (BM * PADK)      // one operand tile
#define BUF_FLOATS  (2 * TILE_FLOATS)
#define DYN_SMEM    (2 * BUF_FLOATS * 4)   // 73728 bytes (A+B, double buffered)

// Scratch (device globals — allocation is forbidden)
__device__ float g_qkv[(size_t)TSEQ * QKVN];   // 96 MB  [T][3*NF] (q|k|v)
__device__ float g_att[(size_t)TSEQ * TSEQ];   // 64 MB
__device__ float g_WT [(size_t)QKVN * CIN];    // 48 MB  W^T
__device__ float g_vT [(size_t)NF   * TSEQ];   // 32 MB  v^T

// ---------------------------------------------------------------------------
// tf32 helpers (plain sm_80+ PTX — no arch-accelerated instructions)
// ---------------------------------------------------------------------------
__device__ __forceinline__ uint32_t f2tf32(float f) {
    uint32_t u;
    asm("cvt.rna.tf32.f32 %0, %1;" : "=r"(u) : "f"(f));
    return u;
}

#define MMA_TF32(d, a, b) \
    asm volatile("mma.sync.aligned.m16n8k8.row.col.f32.tf32.tf32.f32 " \
        "{%0,%1,%2,%3}, {%4,%5,%6,%7}, {%8,%9}, {%0,%1,%2,%3};" \
        : "+f"((d)[0]), "+f"((d)[1]), "+f"((d)[2]), "+f"((d)[3]) \
        : "r"((a)[0]), "r"((a)[1]), "r"((a)[2]), "r"((a)[3]), \
          "r"((b)[0]), "r"((b)[1]))

// ---------------------------------------------------------------------------
// Staging: load 128x32 fp32 tile (K-major, ld = row stride), cvt to tf32 regs.
// 256 threads: each thread one half-row of 16 values (4 x float4).
// ---------------------------------------------------------------------------
struct Pref { uint32_t v[16]; };

__device__ __forceinline__ void ldg_tile(const float* __restrict__ g, int ld, int k0,
                                         int tid, Pref& p) {
    const int row = tid >> 1;
    const int c0 = (tid & 1) << 4;
    const float* gp = g + (size_t)row * ld + k0 + c0;
#pragma unroll
    for (int j = 0; j < 4; j++) {
        float4 v = *(const float4*)(gp + 4 * j);
        p.v[4 * j + 0] = f2tf32(v.x);
        p.v[4 * j + 1] = f2tf32(v.y);
        p.v[4 * j + 2] = f2tf32(v.z);
        p.v[4 * j + 3] = f2tf32(v.w);
    }
}
__device__ __forceinline__ void sts_tile(float* s, int tid, const Pref& p) {
    const int row = tid >> 1;
    const int c0 = (tid & 1) << 4;
    uint32_t* sp = (uint32_t*)(s + row * PADK + c0);
#pragma unroll
    for (int j = 0; j < 4; j++)
        *(uint4*)(sp + 4 * j) = make_uint4(p.v[4*j], p.v[4*j+1], p.v[4*j+2], p.v[4*j+3]);
}

// ---------------------------------------------------------------------------
// Mainloop: acc[2][8][4] += A(128xK) @ B(128xK)^T over nk K-chunks of 32.
// smem: [buf0: A,B][buf1: A,B], each tile 128*PADK floats.
// ---------------------------------------------------------------------------
__device__ __forceinline__ void gemm_mainloop(const float* __restrict__ A, int lda,
                                              const float* __restrict__ B, int ldb,
                                              int kStart, int nk, float* smem,
                                              float acc[2][8][4], int tid) {
    const int lane = tid & 31;
    const int warp = tid >> 5;
    const int wm = warp >> 1;      // 0..3
    const int wn = warp & 1;       // 0..1
    const int fr = lane >> 2;      // 0..7
    const int fc = lane & 3;       // 0..3

    Pref pa, pb;
    ldg_tile(A, lda, kStart, tid, pa);
    ldg_tile(B, ldb, kStart, tid, pb);
    sts_tile(smem, tid, pa);
    sts_tile(smem + TILE_FLOATS, tid, pb);
    __syncthreads();

    for (int i = 0; i < nk; i++) {
        if (i + 1 < nk) {
            const int k = kStart + (i + 1) * BK;
            ldg_tile(A, lda, k, tid, pa);
            ldg_tile(B, ldb, k, tid, pb);
        }
        const float* As = smem + (i & 1) * BUF_FLOATS;
        const float* Bs = As + TILE_FLOATS;
#pragma unroll
        for (int kk = 0; kk < 4; kk++) {
            const int k0 = kk * 8;
            uint32_t afr[2][4], bfr[8][2];
#pragma unroll
            for (int mt = 0; mt < 2; mt++) {
                const uint32_t* ap =
                    (const uint32_t*)(As + (wm * 32 + mt * 16 + fr) * PADK + k0 + fc);
                afr[mt][0] = ap[0];
                afr[mt][1] = ap[8 * PADK];
                afr[mt][2] = ap[4];
                afr[mt][3] = ap[8 * PADK + 4];
            }
#pragma unroll
            for (int nt = 0; nt < 8; nt++) {
                const uint32_t* bp =
                    (const uint32_t*)(Bs + (wn * 64 + nt * 8 + fr) * PADK + k0 + fc);
                bfr[nt][0] = bp[0];
                bfr[nt][1] = bp[4];
            }
#pragma unroll
            for (int mt = 0; mt < 2; mt++)
#pragma unroll
                for (int nt = 0; nt < 8; nt++)
                    MMA_TF32(acc[mt][nt], afr[mt], bfr[nt]);
        }
        __syncthreads();
        if (i + 1 < nk) {
            float* Ad = smem + ((i + 1) & 1) * BUF_FLOATS;
            sts_tile(Ad, tid, pa);
            sts_tile(Ad + TILE_FLOATS, tid, pb);
            __syncthreads();
        }
    }
}

// Epilogue index helper: element (mt, nt, d-pair) coordinates
// row0 = wm*32 + mt*16 + (lane>>2), row1 = row0+8
// col  = wn*64 + nt*8 + (lane&3)*2   (d0,d1) ; (d2,d3) at row1

// ---------------------------------------------------------------------------
// GEMM 1: qkv = x @ WT^T + b     grid (48, 32)
// ---------------------------------------------------------------------------
__global__ __launch_bounds__(256, 1) void k_qkv_tc(const float* __restrict__ X,
                                                   const float* __restrict__ bias) {
    extern __shared__ float smem[];
    const int tid = threadIdx.x;
    const int bx = blockIdx.x, by = blockIdx.y;
    float acc[2][8][4] = {};
    gemm_mainloop(X + (size_t)by * BM * CIN, CIN,
                  g_WT + (size_t)bx * BN * CIN, CIN, 0, CIN / BK, smem, acc, tid);

    const int lane = tid & 31, warp = tid >> 5;
    const int wm = warp >> 1, wn = warp & 1;
#pragma unroll
    for (int mt = 0; mt < 2; mt++) {
        const int r0 = by * BM + wm * 32 + mt * 16 + (lane >> 2);
#pragma unroll
        for (int nt = 0; nt < 8; nt++) {
            const int col = bx * BN + wn * 64 + nt * 8 + (lane & 3) * 2;
            const float b0 = bias[col], b1 = bias[col + 1];
            *(float2*)(g_qkv + (size_t)r0 * QKVN + col) =
                make_float2(acc[mt][nt][0] + b0, acc[mt][nt][1] + b1);
            *(float2*)(g_qkv + (size_t)(r0 + 8) * QKVN + col) =
                make_float2(acc[mt][nt][2] + b0, acc[mt][nt][3] + b1);
        }
    }
}

// ---------------------------------------------------------------------------
// GEMM 2: att = mask(q @ k^T * scale)   grid (32, 32)
// ---------------------------------------------------------------------------
__global__ __launch_bounds__(256, 1) void k_att_tc(const int* __restrict__ npadd_p) {
    extern __shared__ float smem[];
    const int tid = threadIdx.x;
    const int bx = blockIdx.x, by = blockIdx.y;
    const int n_padd = *npadd_p;
    const int rowMax = by * BM + BM - 1;
    const int colMin = bx * BN;

    if (colMin > rowMax || rowMax < n_padd || colMin + BN - 1 < n_padd) {
        const float4 negv = make_float4(NEGV, NEGV, NEGV, NEGV);
        for (int i = tid; i < BM * BN / 4; i += 256) {
            int m = i >> 5, n = (i & 31) << 2;
            *(float4*)(g_att + (size_t)(by * BM + m) * TSEQ + colMin + n) = negv;
        }
        return;
    }

    float acc[2][8][4] = {};
    gemm_mainloop(g_qkv + (size_t)by * BM * QKVN, QKVN,
                  g_qkv + (size_t)bx * BN * QKVN + NF, QKVN, 0, NF / BK, smem, acc, tid);

    const float scale = 0.022097086912079608f;  // 1/sqrt(2048)
    const int lane = tid & 31, warp = tid >> 5;
    const int wm = warp >> 1, wn = warp & 1;
#pragma unroll
    for (int mt = 0; mt < 2; mt++) {
        const int r0 = by * BM + wm * 32 + mt * 16 + (lane >> 2);
        const int r1 = r0 + 8;
#pragma unroll
        for (int nt = 0; nt < 8; nt++) {
            const int col = bx * BN + wn * 64 + nt * 8 + (lane & 3) * 2;
            float2 o0, o1;
            o0.x = (r0 >= n_padd && col     <= r0 && col     >= n_padd) ? acc[mt][nt][0] * scale : NEGV;
            o0.y = (r0 >= n_padd && col + 1 <= r0 && col + 1 >= n_padd) ? acc[mt][nt][1] * scale : NEGV;
            o1.x = (r1 >= n_padd && col     <= r1 && col     >= n_padd) ? acc[mt][nt][2] * scale : NEGV;
            o1.y = (r1 >= n_padd && col + 1 <= r1 && col + 1 >= n_padd) ? acc[mt][nt][3] * scale : NEGV;
            *(float2*)(g_att + (size_t)r0 * TSEQ + col) = o0;
            *(float2*)(g_att + (size_t)r1 * TSEQ + col) = o1;
        }
    }
}

// ---------------------------------------------------------------------------
// GEMM 3: y = p @ vT^T   grid (16, 32); K starts at padding, capped causally
// ---------------------------------------------------------------------------
__global__ __launch_bounds__(256, 1) void k_out_tc(float* __restrict__ Y,
                                                   const int* __restrict__ npadd_p) {
    extern __shared__ float smem[];
    const int tid = threadIdx.x;
    const int bx = blockIdx.x, by = blockIdx.y;
    const int n_padd = *npadd_p;
    const int kStart = n_padd & ~(BK - 1);
    const int nk = ((by + 1) * BM - kStart) / BK;

    if (nk <= 0) {
        const float4 z = make_float4(0.f, 0.f, 0.f, 0.f);
        for (int i = tid; i < BM * BN / 4; i += 256) {
            int m = i >> 5, n = (i & 31) << 2;
            *(float4*)(Y + (size_t)(by * BM + m) * NF + bx * BN + n) = z;
        }
        return;
    }

    float acc[2][8][4] = {};
    gemm_mainloop(g_att + (size_t)by * BM * TSEQ, TSEQ,
                  g_vT + (size_t)bx * BN * TSEQ, TSEQ, kStart, nk, smem, acc, tid);

    const int lane = tid & 31, warp = tid >> 5;
    const int wm = warp >> 1, wn = warp & 1;
#pragma unroll
    for (int mt = 0; mt < 2; mt++) {
        const int r0 = by * BM + wm * 32 + mt * 16 + (lane >> 2);
#pragma unroll
        for (int nt = 0; nt < 8; nt++) {
            const int col = bx * BN + wn * 64 + nt * 8 + (lane & 3) * 2;
            *(float2*)(Y + (size_t)r0 * NF + col) =
                make_float2(acc[mt][nt][0], acc[mt][nt][1]);
            *(float2*)(Y + (size_t)(r0 + 8) * NF + col) =
                make_float2(acc[mt][nt][2], acc[mt][nt][3]);
        }
    }
}

// ---------------------------------------------------------------------------
// Transpose: dst[c][r] = src[r][c]
// ---------------------------------------------------------------------------
__global__ void k_transpose(const float* __restrict__ src, float* __restrict__ dst,
                            int lds, int ldd) {
    __shared__ float t[32][33];
    const int bx = blockIdx.x * 32, by = blockIdx.y * 32;
    const int x = threadIdx.x, y = threadIdx.y;
#pragma unroll
    for (int j = 0; j < 32; j += 8)
        t[y + j][x] = src[(size_t)(by + y + j) * lds + bx + x];
    __syncthreads();
#pragma unroll
    for (int j = 0; j < 32; j += 8)
        dst[(size_t)(bx + y + j) * ldd + by + x] = t[x][y + j];
}

// ---------------------------------------------------------------------------
// Row softmax in place (padding rows -> 0)
// ---------------------------------------------------------------------------
__global__ __launch_bounds__(256) void k_softmax(const int* __restrict__ npadd_p) {
    const int r = blockIdx.x;
    const int n_padd = *npadd_p;
    float* row = g_att + (size_t)r * TSEQ;
    const int tid = threadIdx.x;
    if (r < n_padd) {
        const float4 z = make_float4(0.f, 0.f, 0.f, 0.f);
        for (int c = tid * 4; c < TSEQ; c += 256 * 4) *(float4*)(row + c) = z;
        return;
    }
    __shared__ float redmax[8], redsum[8];
    float vals[TSEQ / 256];
    float mx = NEGV;
#pragma unroll
    for (int i = 0; i < TSEQ / 256; i++) {
        vals[i] = row[tid + i * 256];
        mx = fmaxf(mx, vals[i]);
    }
#pragma unroll
    for (int o = 16; o > 0; o >>= 1) mx = fmaxf(mx, __shfl_xor_sync(0xffffffffu, mx, o));
    if ((tid & 31) == 0) redmax[tid >> 5] = mx;
    __syncthreads();
    mx = redmax[0];
#pragma unroll
    for (int i = 1; i < 8; i++) mx = fmaxf(mx, redmax[i]);
    float s = 0.f;
#pragma unroll
    for (int i = 0; i < TSEQ / 256; i++) {
        vals[i] = expf(vals[i] - mx);
        s += vals[i];
    }
#pragma unroll
    for (int o = 16; o > 0; o >>= 1) s += __shfl_xor_sync(0xffffffffu, s, o);
    if ((tid & 31) == 0) redsum[tid >> 5] = s;
    __syncthreads();
    s = redsum[0];
#pragma unroll
    for (int i = 1; i < 8; i++) s += redsum[i];
    const float inv = 1.f / s;
#pragma unroll
    for (int i = 0; i < TSEQ / 256; i++) row[tid + i * 256] = vals[i] * inv;
}

// ---------------------------------------------------------------------------
extern "C" void kernel_launch(void* const* d_in, const int* in_sizes, int n_in,
                              void* d_out, int out_size) {
    const float* x  = (const float*)d_in[0];
    const float* W  = (const float*)d_in[1];
    const float* b  = (const float*)d_in[2];
    const int* npad = (const int*)d_in[3];
    float* y = (float*)d_out;

    cudaFuncSetAttribute(k_qkv_tc, cudaFuncAttributeMaxDynamicSharedMemorySize, DYN_SMEM);
    cudaFuncSetAttribute(k_att_tc, cudaFuncAttributeMaxDynamicSharedMemorySize, DYN_SMEM);
    cudaFuncSetAttribute(k_out_tc, cudaFuncAttributeMaxDynamicSharedMemorySize, DYN_SMEM);

    float *wt_p, *vt_p, *qkv_p;
    cudaGetSymbolAddress((void**)&wt_p, g_WT);
    cudaGetSymbolAddress((void**)&vt_p, g_vT);
    cudaGetSymbolAddress((void**)&qkv_p, g_qkv);

    dim3 tb(32, 8);
    // W (2048 x 6144) -> WT (6144 x 2048)
    k_transpose<<<dim3(QKVN / 32, CIN / 32), tb>>>(W, wt_p, QKVN, CIN);
    k_qkv_tc<<<dim3(QKVN / BN, TSEQ / BM), 256, DYN_SMEM>>>(x, b);
    // v = qkv[:, 2NF:] (4096 x 2048) -> vT (2048 x 4096)
    k_transpose<<<dim3(NF / 32, TSEQ / 32), tb>>>(qkv_p + 2 * NF, vt_p, QKVN, TSEQ);
    k_att_tc<<<dim3(TSEQ / BN, TSEQ / BM), 256, DYN_SMEM>>>(npad);
    k_softmax<<<TSEQ, 256>>>(npad);
    k_out_tc<<<dim3(NF / BN, TSEQ / BM), 256, DYN_SMEM>>>(y, npad);
}

// round 6
// speedup vs baseline: 3.6741x; 1.8023x over previous
#include <cuda_runtime.h>
#include <cstdint>

// Problem dims (fixed)
#define TSEQ 4096
#define CIN  2048
#define NF   2048
#define QKVN 6144
#define NEGV -1e30f

// GEMM tiling
#define BM 128
#define BN 128
#define BK 32
#define PADK 36                      // smem row stride (floats); 144B rows keep 16B align
#define TILE_FLOATS (BM * PADK)
#define BUF_FLOATS  (2 * TILE_FLOATS)          // A + B for one stage
#define DYN_SMEM    (2 * BUF_FLOATS * 4)       // 73728 B (2 stages)

// Scratch (device globals — allocation is forbidden)
__device__ float g_qkv[(size_t)TSEQ * QKVN];   // 96 MB  [T][3*NF] (q|k|v), tf32-valued
__device__ float g_att[(size_t)TSEQ * TSEQ];   // 64 MB  att / probs (probs tf32-valued)
__device__ float g_WT [(size_t)QKVN * CIN];    // 48 MB  W^T, tf32-valued
__device__ float g_vT [(size_t)NF   * TSEQ];   // 32 MB  v^T, tf32-valued
__device__ float g_xr [(size_t)TSEQ * CIN];    // 32 MB  x rounded to tf32

// ---------------------------------------------------------------------------
// helpers
// ---------------------------------------------------------------------------
__device__ __forceinline__ uint32_t f2tf32(float f) {
    uint32_t u;
    asm("cvt.rna.tf32.f32 %0, %1;" : "=r"(u) : "f"(f));
    return u;
}
__device__ __forceinline__ float rnd_tf32(float f) { return __uint_as_float(f2tf32(f)); }

__device__ __forceinline__ uint32_t smem_u32(const void* p) {
    uint32_t a;
    asm("{ .reg .u64 t; cvta.to.shared.u64 t, %1; cvt.u32.u64 %0, t; }" : "=r"(a) : "l"(p));
    return a;
}

#define CP16(sa, gp) asm volatile("cp.async.cg.shared.global [%0], [%1], 16;" :: "r"(sa), "l"(gp))
#define CP_COMMIT()  asm volatile("cp.async.commit_group;" ::: "memory")
#define CP_WAIT(n)   asm volatile("cp.async.wait_group %0;" :: "n"(n) : "memory")

#define MMA_TF32(d, a, b) \
    asm volatile("mma.sync.aligned.m16n8k8.row.col.f32.tf32.tf32.f32 " \
        "{%0,%1,%2,%3}, {%4,%5,%6,%7}, {%8,%9}, {%0,%1,%2,%3};" \
        : "+f"((d)[0]), "+f"((d)[1]), "+f"((d)[2]), "+f"((d)[3]) \
        : "r"((a)[0]), "r"((a)[1]), "r"((a)[2]), "r"((a)[3]), \
          "r"((b)[0]), "r"((b)[1]))

// ---------------------------------------------------------------------------
// Stage one 128x32 fp32 tile (K-major) into smem via cp.async. 256 threads,
// 4 x 16B per thread.
// ---------------------------------------------------------------------------
__device__ __forceinline__ void stage_cp(const float* __restrict__ g, int ld, int k0,
                                         uint32_t sbase, int tid) {
#pragma unroll
    for (int j = 0; j < 4; j++) {
        const int idx = tid + 256 * j;
        const int r = idx >> 3, c = (idx & 7) << 2;
        CP16(sbase + (uint32_t)(r * PADK + c) * 4u, g + (size_t)r * ld + k0 + c);
    }
}

// ---------------------------------------------------------------------------
// Compute one K-chunk from smem buffer into acc.
// ---------------------------------------------------------------------------
__device__ __forceinline__ void compute_chunk(const float* As, const float* Bs,
                                              float acc[2][8][4], int lane, int wm, int wn) {
    const int fr = lane >> 2, fc = lane & 3;
#pragma unroll
    for (int kk = 0; kk < 4; kk++) {
        const int k0 = kk * 8;
        uint32_t afr[2][4], bfr[8][2];
#pragma unroll
        for (int mt = 0; mt < 2; mt++) {
            const uint32_t* ap =
                (const uint32_t*)(As + (wm * 32 + mt * 16 + fr) * PADK + k0 + fc);
            afr[mt][0] = ap[0];
            afr[mt][1] = ap[8 * PADK];
            afr[mt][2] = ap[4];
            afr[mt][3] = ap[8 * PADK + 4];
        }
#pragma unroll
        for (int nt = 0; nt < 8; nt++) {
            const uint32_t* bp =
                (const uint32_t*)(Bs + (wn * 64 + nt * 8 + fr) * PADK + k0 + fc);
            bfr[nt][0] = bp[0];
            bfr[nt][1] = bp[4];
        }
#pragma unroll
        for (int mt = 0; mt < 2; mt++)
#pragma unroll
            for (int nt = 0; nt < 8; nt++)
                MMA_TF32(acc[mt][nt], afr[mt], bfr[nt]);
    }
}

// ---------------------------------------------------------------------------
// Mainloop: acc += A(128xK) @ B(128xK)^T over nk chunks of 32, cp.async 2-stage.
// ---------------------------------------------------------------------------
__device__ __forceinline__ void gemm_mainloop(const float* __restrict__ A, int lda,
                                              const float* __restrict__ B, int ldb,
                                              int kStart, int nk, float* smem,
                                              float acc[2][8][4], int tid) {
    const int lane = tid & 31, warp = tid >> 5;
    const int wm = warp >> 1, wn = warp & 1;
    const uint32_t s0 = smem_u32(smem);

    stage_cp(A, lda, kStart, s0, tid);
    stage_cp(B, ldb, kStart, s0 + TILE_FLOATS * 4, tid);
    CP_COMMIT();
    if (nk > 1) {
        stage_cp(A, lda, kStart + BK, s0 + BUF_FLOATS * 4, tid);
        stage_cp(B, ldb, kStart + BK, s0 + (BUF_FLOATS + TILE_FLOATS) * 4, tid);
        CP_COMMIT();
    }
    for (int i = 0; i < nk; i++) {
        if (i + 1 < nk) { CP_WAIT(1); } else { CP_WAIT(0); }
        __syncthreads();
        const float* As = smem + (i & 1) * BUF_FLOATS;
        compute_chunk(As, As + TILE_FLOATS, acc, lane, wm, wn);
        __syncthreads();
        if (i + 2 < nk) {
            const uint32_t nb = s0 + (uint32_t)((i & 1) * BUF_FLOATS) * 4u;
            const int k = kStart + (i + 2) * BK;
            stage_cp(A, lda, k, nb, tid);
            stage_cp(B, ldb, k, nb + TILE_FLOATS * 4, tid);
            CP_COMMIT();
        }
    }
}

// Epilogue coords: row0 = wm*32+mt*16+(lane>>2), row1=row0+8;
//                  col = wn*64+nt*8+(lane&3)*2; acc = {d0,d1 @row0; d2,d3 @row1}

// ---------------------------------------------------------------------------
// GEMM 1: qkv = xr @ WT^T + b   grid (48, 32)  — writes tf32-valued outputs
// ---------------------------------------------------------------------------
__global__ __launch_bounds__(256, 2) void k_qkv_tc(const float* __restrict__ bias) {
    extern __shared__ float smem[];
    const int tid = threadIdx.x;
    const int bx = blockIdx.x, by = blockIdx.y;
    float acc[2][8][4] = {};
    gemm_mainloop(g_xr + (size_t)by * BM * CIN, CIN,
                  g_WT + (size_t)bx * BN * CIN, CIN, 0, CIN / BK, smem, acc, tid);

    const int lane = tid & 31, warp = tid >> 5;
    const int wm = warp >> 1, wn = warp & 1;
#pragma unroll
    for (int mt = 0; mt < 2; mt++) {
        const int r0 = by * BM + wm * 32 + mt * 16 + (lane >> 2);
#pragma unroll
        for (int nt = 0; nt < 8; nt++) {
            const int col = bx * BN + wn * 64 + nt * 8 + (lane & 3) * 2;
            const float b0 = bias[col], b1 = bias[col + 1];
            *(float2*)(g_qkv + (size_t)r0 * QKVN + col) =
                make_float2(rnd_tf32(acc[mt][nt][0] + b0), rnd_tf32(acc[mt][nt][1] + b1));
            *(float2*)(g_qkv + (size_t)(r0 + 8) * QKVN + col) =
                make_float2(rnd_tf32(acc[mt][nt][2] + b0), rnd_tf32(acc[mt][nt][3] + b1));
        }
    }
}

// ---------------------------------------------------------------------------
// GEMM 2: att = mask(q @ k^T * scale)  grid (32, 32)
//   bx > by           : never read downstream -> skip entirely
//   all rows padding  : never read -> skip
//   all cols < n_padd : NEG fill only
// ---------------------------------------------------------------------------
__global__ __launch_bounds__(256, 2) void k_att_tc(const int* __restrict__ npadd_p) {
    extern __shared__ float smem[];
    const int tid = threadIdx.x;
    const int bx = blockIdx.x, by = blockIdx.y;
    if (bx > by) return;
    const int n_padd = *npadd_p;
    const int rowMax = by * BM + BM - 1;
    const int colMin = bx * BN, colMax = colMin + BN - 1;
    if (rowMax < n_padd) return;
    if (colMax < n_padd) {
        const float4 negv = make_float4(NEGV, NEGV, NEGV, NEGV);
        for (int i = tid; i < BM * BN / 4; i += 256) {
            int m = i >> 5, n = (i & 31) << 2;
            *(float4*)(g_att + (size_t)(by * BM + m) * TSEQ + colMin + n) = negv;
        }
        return;
    }

    float acc[2][8][4] = {};
    gemm_mainloop(g_qkv + (size_t)by * BM * QKVN, QKVN,
                  g_qkv + (size_t)bx * BN * QKVN + NF, QKVN, 0, NF / BK, smem, acc, tid);

    const float scale = 0.022097086912079608f;  // 1/sqrt(2048)
    const int lane = tid & 31, warp = tid >> 5;
    const int wm = warp >> 1, wn = warp & 1;
#pragma unroll
    for (int mt = 0; mt < 2; mt++) {
        const int r0 = by * BM + wm * 32 + mt * 16 + (lane >> 2);
        const int r1 = r0 + 8;
#pragma unroll
        for (int nt = 0; nt < 8; nt++) {
            const int col = bx * BN + wn * 64 + nt * 8 + (lane & 3) * 2;
            float2 o0, o1;
            o0.x = (r0 >= n_padd && col     <= r0 && col     >= n_padd) ? acc[mt][nt][0] * scale : NEGV;
            o0.y = (r0 >= n_padd && col + 1 <= r0 && col + 1 >= n_padd) ? acc[mt][nt][1] * scale : NEGV;
            o1.x = (r1 >= n_padd && col     <= r1 && col     >= n_padd) ? acc[mt][nt][2] * scale : NEGV;
            o1.y = (r1 >= n_padd && col + 1 <= r1 && col + 1 >= n_padd) ? acc[mt][nt][3] * scale : NEGV;
            *(float2*)(g_att + (size_t)r0 * TSEQ + col) = o0;
            *(float2*)(g_att + (size_t)r1 * TSEQ + col) = o1;
        }
    }
}

// ---------------------------------------------------------------------------
// GEMM 3: y = p @ vT^T   grid (16, 32); K in [n_padd&~31, (by+1)*128)
// ---------------------------------------------------------------------------
__global__ __launch_bounds__(256, 2) void k_out_tc(float* __restrict__ Y,
                                                   const int* __restrict__ npadd_p) {
    extern __shared__ float smem[];
    const int tid = threadIdx.x;
    const int bx = blockIdx.x, by = blockIdx.y;
    const int n_padd = *npadd_p;
    const int kStart = n_padd & ~(BK - 1);
    const int nk = ((by + 1) * BM - kStart) / BK;

    if (nk <= 0) {
        const float4 z = make_float4(0.f, 0.f, 0.f, 0.f);
        for (int i = tid; i < BM * BN / 4; i += 256) {
            int m = i >> 5, n = (i & 31) << 2;
            *(float4*)(Y + (size_t)(by * BM + m) * NF + bx * BN + n) = z;
        }
        return;
    }

    float acc[2][8][4] = {};
    gemm_mainloop(g_att + (size_t)by * BM * TSEQ, TSEQ,
                  g_vT + (size_t)bx * BN * TSEQ, TSEQ, kStart, nk, smem, acc, tid);

    const int lane = tid & 31, warp = tid >> 5;
    const int wm = warp >> 1, wn = warp & 1;
#pragma unroll
    for (int mt = 0; mt < 2; mt++) {
        const int r0 = by * BM + wm * 32 + mt * 16 + (lane >> 2);
#pragma unroll
        for (int nt = 0; nt < 8; nt++) {
            const int col = bx * BN + wn * 64 + nt * 8 + (lane & 3) * 2;
            *(float2*)(Y + (size_t)r0 * NF + col) =
                make_float2(acc[mt][nt][0], acc[mt][nt][1]);
            *(float2*)(Y + (size_t)(r0 + 8) * NF + col) =
                make_float2(acc[mt][nt][2], acc[mt][nt][3]);
        }
    }
}

// ---------------------------------------------------------------------------
// Transpose + round: dst[c][r] = tf32(src[r][c])
// ---------------------------------------------------------------------------
__global__ void k_transpose(const float* __restrict__ src, float* __restrict__ dst,
                            int lds, int ldd) {
    __shared__ float t[32][33];
    const int bx = blockIdx.x * 32, by = blockIdx.y * 32;
    const int x = threadIdx.x, y = threadIdx.y;
#pragma unroll
    for (int j = 0; j < 32; j += 8)
        t[y + j][x] = rnd_tf32(src[(size_t)(by + y + j) * lds + bx + x]);
    __syncthreads();
#pragma unroll
    for (int j = 0; j < 32; j += 8)
        dst[(size_t)(bx + y + j) * ldd + by + x] = t[x][y + j];
}

// Round-copy: g_xr = tf32(x)
__global__ void k_roundcpy(const float* __restrict__ src, float* __restrict__ dst, int n4) {
    int i = blockIdx.x * blockDim.x + threadIdx.x;
    if (i < n4) {
        float4 v = ((const float4*)src)[i];
        v.x = rnd_tf32(v.x); v.y = rnd_tf32(v.y);
        v.z = rnd_tf32(v.z); v.w = rnd_tf32(v.w);
        ((float4*)dst)[i] = v;
    }
}

// ---------------------------------------------------------------------------
// Row softmax: only the causal prefix [0, ceil128(r+1)) is read/written.
// Writes tf32-rounded probabilities. Padding rows -> zeros on the prefix.
// ---------------------------------------------------------------------------
__global__ __launch_bounds__(256) void k_softmax(const int* __restrict__ npadd_p) {
    const int r = blockIdx.x;
    const int n_padd = *npadd_p;
    const int cap = ((r >> 7) + 1) << 7;       // multiple of 128, > r
    float* row = g_att + (size_t)r * TSEQ;
    const int tid = threadIdx.x;
    if (r < n_padd) {
        for (int c = tid * 4; c < cap; c += 256 * 4)
            *(float4*)(row + c) = make_float4(0.f, 0.f, 0.f, 0.f);
        return;
    }
    __shared__ float redmax[8], redsum[8];
    float vals[16];
    float mx = NEGV;
#pragma unroll
    for (int i = 0; i < 16; i++) {
        const int c = tid + i * 256;
        vals[i] = (c < cap) ? row[c] : NEGV;
        mx = fmaxf(mx, vals[i]);
    }
#pragma unroll
    for (int o = 16; o > 0; o >>= 1) mx = fmaxf(mx, __shfl_xor_sync(0xffffffffu, mx, o));
    if ((tid & 31) == 0) redmax[tid >> 5] = mx;
    __syncthreads();
    mx = redmax[0];
#pragma unroll
    for (int i = 1; i < 8; i++) mx = fmaxf(mx, redmax[i]);
    float s = 0.f;
#pragma unroll
    for (int i = 0; i < 16; i++) {
        vals[i] = expf(vals[i] - mx);      // exp(NEG - mx) underflows to 0
        s += vals[i];
    }
#pragma unroll
    for (int o = 16; o > 0; o >>= 1) s += __shfl_xor_sync(0xffffffffu, s, o);
    if ((tid & 31) == 0) redsum[tid >> 5] = s;
    __syncthreads();
    s = redsum[0];
#pragma unroll
    for (int i = 1; i < 8; i++) s += redsum[i];
    const float inv = 1.f / s;
#pragma unroll
    for (int i = 0; i < 16; i++) {
        const int c = tid + i * 256;
        if (c < cap) row[c] = rnd_tf32(vals[i] * inv);
    }
}

// ---------------------------------------------------------------------------
extern "C" void kernel_launch(void* const* d_in, const int* in_sizes, int n_in,
                              void* d_out, int out_size) {
    const float* x  = (const float*)d_in[0];
    const float* W  = (const float*)d_in[1];
    const float* b  = (const float*)d_in[2];
    const int* npad = (const int*)d_in[3];
    float* y = (float*)d_out;

    cudaFuncSetAttribute(k_qkv_tc, cudaFuncAttributeMaxDynamicSharedMemorySize, DYN_SMEM);
    cudaFuncSetAttribute(k_att_tc, cudaFuncAttributeMaxDynamicSharedMemorySize, DYN_SMEM);
    cudaFuncSetAttribute(k_out_tc, cudaFuncAttributeMaxDynamicSharedMemorySize, DYN_SMEM);

    float *wt_p, *vt_p, *qkv_p, *xr_p;
    cudaGetSymbolAddress((void**)&wt_p, g_WT);
    cudaGetSymbolAddress((void**)&vt_p, g_vT);
    cudaGetSymbolAddress((void**)&qkv_p, g_qkv);
    cudaGetSymbolAddress((void**)&xr_p, g_xr);

    dim3 tb(32, 8);
    const int nx4 = TSEQ * CIN / 4;
    k_roundcpy<<<(nx4 + 255) / 256, 256>>>(x, xr_p, nx4);
    // W (2048 x 6144) -> WT (6144 x 2048), rounded
    k_transpose<<<dim3(QKVN / 32, CIN / 32), tb>>>(W, wt_p, QKVN, CIN);
    k_qkv_tc<<<dim3(QKVN / BN, TSEQ / BM), 256, DYN_SMEM>>>(b);
    // v = qkv[:, 2NF:] (4096 x 2048) -> vT (2048 x 4096)
    k_transpose<<<dim3(NF / 32, TSEQ / 32), tb>>>(qkv_p + 2 * NF, vt_p, QKVN, TSEQ);
    k_att_tc<<<dim3(TSEQ / BN, TSEQ / BM), 256, DYN_SMEM>>>(npad);
    k_softmax<<<TSEQ, 256>>>(npad);
    k_out_tc<<<dim3(NF / BN, TSEQ / BM), 256, DYN_SMEM>>>(y, npad);
}

// round 7
// speedup vs baseline: 3.8770x; 1.0552x over previous
#include <cuda_runtime.h>
#include <cstdint>

// Problem dims (fixed)
#define TSEQ 4096
#define CIN  2048
#define NF   2048
#define QKVN 6144
#define NEGV -1e30f

// GEMM tiling
#define BM 128
#define BN 128
#define BK 32
#define PADK 36                      // smem row stride (floats); 144B rows keep 16B align
#define NSTAGE 3
#define TILE_FLOATS (BM * PADK)
#define BUF_FLOATS  (2 * TILE_FLOATS)              // A + B for one stage
#define DYN_SMEM    (NSTAGE * BUF_FLOATS * 4)      // 110592 B

// Scratch (device globals — allocation is forbidden; zero-initialized at load)
__device__ float g_qkv[(size_t)TSEQ * QKVN];   // 96 MB  [T][3*NF] (q|k|v), tf32-valued
__device__ float g_att[(size_t)TSEQ * TSEQ];   // 64 MB  att / probs (probs tf32-valued)
__device__ float g_WT [(size_t)QKVN * CIN];    // 48 MB  W^T, tf32-valued
__device__ float g_vT [(size_t)NF   * TSEQ];   // 32 MB  v^T, tf32-valued
__device__ float g_xr [(size_t)TSEQ * CIN];    // 32 MB  x rounded to tf32

// ---------------------------------------------------------------------------
// helpers
// ---------------------------------------------------------------------------
__device__ __forceinline__ uint32_t f2tf32(float f) {
    uint32_t u;
    asm("cvt.rna.tf32.f32 %0, %1;" : "=r"(u) : "f"(f));
    return u;
}
__device__ __forceinline__ float rnd_tf32(float f) { return __uint_as_float(f2tf32(f)); }

__device__ __forceinline__ uint32_t smem_u32(const void* p) {
    uint32_t a;
    asm("{ .reg .u64 t; cvta.to.shared.u64 t, %1; cvt.u32.u64 %0, t; }" : "=r"(a) : "l"(p));
    return a;
}

#define CP16(sa, gp) asm volatile("cp.async.cg.shared.global [%0], [%1], 16;" :: "r"(sa), "l"(gp))
#define CP_COMMIT()  asm volatile("cp.async.commit_group;" ::: "memory")
#define CP_WAIT(n)   asm volatile("cp.async.wait_group %0;" :: "n"(n) : "memory")

#define MMA_TF32(d, a, b) \
    asm volatile("mma.sync.aligned.m16n8k8.row.col.f32.tf32.tf32.f32 " \
        "{%0,%1,%2,%3}, {%4,%5,%6,%7}, {%8,%9}, {%0,%1,%2,%3};" \
        : "+f"((d)[0]), "+f"((d)[1]), "+f"((d)[2]), "+f"((d)[3]) \
        : "r"((a)[0]), "r"((a)[1]), "r"((a)[2]), "r"((a)[3]), \
          "r"((b)[0]), "r"((b)[1]))

// ---------------------------------------------------------------------------
// Stage one 128x32 fp32 tile (K-major) into smem via cp.async. 256 threads,
// 4 x 16B per thread.
// ---------------------------------------------------------------------------
__device__ __forceinline__ void stage_cp(const float* __restrict__ g, int ld, int k0,
                                         uint32_t sbase, int tid) {
#pragma unroll
    for (int j = 0; j < 4; j++) {
        const int idx = tid + 256 * j;
        const int r = idx >> 3, c = (idx & 7) << 2;
        CP16(sbase + (uint32_t)(r * PADK + c) * 4u, g + (size_t)r * ld + k0 + c);
    }
}

// ---------------------------------------------------------------------------
// Compute one K-chunk from smem buffer into acc.
// ---------------------------------------------------------------------------
__device__ __forceinline__ void compute_chunk(const float* As, const float* Bs,
                                              float acc[2][8][4], int lane, int wm, int wn) {
    const int fr = lane >> 2, fc = lane & 3;
#pragma unroll
    for (int kk = 0; kk < 4; kk++) {
        const int k0 = kk * 8;
        uint32_t afr[2][4], bfr[8][2];
#pragma unroll
        for (int mt = 0; mt < 2; mt++) {
            const uint32_t* ap =
                (const uint32_t*)(As + (wm * 32 + mt * 16 + fr) * PADK + k0 + fc);
            afr[mt][0] = ap[0];
            afr[mt][1] = ap[8 * PADK];
            afr[mt][2] = ap[4];
            afr[mt][3] = ap[8 * PADK + 4];
        }
#pragma unroll
        for (int nt = 0; nt < 8; nt++) {
            const uint32_t* bp =
                (const uint32_t*)(Bs + (wn * 64 + nt * 8 + fr) * PADK + k0 + fc);
            bfr[nt][0] = bp[0];
            bfr[nt][1] = bp[4];
        }
#pragma unroll
        for (int mt = 0; mt < 2; mt++)
#pragma unroll
            for (int nt = 0; nt < 8; nt++)
                MMA_TF32(acc[mt][nt], afr[mt], bfr[nt]);
    }
}

// ---------------------------------------------------------------------------
// Mainloop: acc += A(128xK) @ B(128xK)^T over nk chunks of 32.
// 3-stage cp.async pipeline, one __syncthreads per chunk. Empty commit groups
// at the tail keep the in-flight group count == NSTAGE-1 so CP_WAIT(NSTAGE-2)
// always guarantees the current buffer is complete.
// ---------------------------------------------------------------------------
__device__ __forceinline__ void gemm_mainloop(const float* __restrict__ A, int lda,
                                              const float* __restrict__ B, int ldb,
                                              int kStart, int nk, float* smem,
                                              float acc[2][8][4], int tid) {
    const int lane = tid & 31, warp = tid >> 5;
    const int wm = warp >> 1, wn = warp & 1;
    const uint32_t s0 = smem_u32(smem);

    // Prologue: fill NSTAGE-1 stages (pad with empty groups if nk is small)
#pragma unroll
    for (int s = 0; s < NSTAGE - 1; s++) {
        if (s < nk) {
            const uint32_t sb = s0 + (uint32_t)(s * BUF_FLOATS) * 4u;
            stage_cp(A, lda, kStart + s * BK, sb, tid);
            stage_cp(B, ldb, kStart + s * BK, sb + TILE_FLOATS * 4, tid);
        }
        CP_COMMIT();
    }

    for (int i = 0; i < nk; i++) {
        CP_WAIT(NSTAGE - 2);          // buffer i%NSTAGE complete
        __syncthreads();              // also: all warps done reading buf (i-1)%NSTAGE
        // stage chunk i+NSTAGE-1 into the buffer consumed at iter i-1
        if (i + NSTAGE - 1 < nk) {
            const int s = (i + NSTAGE - 1) % NSTAGE;
            const uint32_t sb = s0 + (uint32_t)(s * BUF_FLOATS) * 4u;
            stage_cp(A, lda, kStart + (i + NSTAGE - 1) * BK, sb, tid);
            stage_cp(B, ldb, kStart + (i + NSTAGE - 1) * BK, sb + TILE_FLOATS * 4, tid);
        }
        CP_COMMIT();                  // (possibly empty) keeps in-flight uniform
        const float* As = smem + (i % NSTAGE) * BUF_FLOATS;
        compute_chunk(As, As + TILE_FLOATS, acc, lane, wm, wn);
    }
}

// Epilogue coords: row0 = wm*32+mt*16+(lane>>2), row1=row0+8;
//                  col = wn*64+nt*8+(lane&3)*2; acc = {d0,d1 @row0; d2,d3 @row1}

// ---------------------------------------------------------------------------
// GEMM 1: qkv = xr @ WT^T + b   grid (48, 32)  — writes tf32-valued outputs
// Skips row-blocks that are entirely padding (their q/k never read; their v
// only multiplies p==0 and unwritten scratch is zero-initialized).
// ---------------------------------------------------------------------------
__global__ __launch_bounds__(256, 2) void k_qkv_tc(const float* __restrict__ bias,
                                                   const int* __restrict__ npadd_p) {
    extern __shared__ float smem[];
    const int tid = threadIdx.x;
    const int bx = blockIdx.x, by = blockIdx.y;
    if ((by + 1) * BM <= *npadd_p) return;
    float acc[2][8][4] = {};
    gemm_mainloop(g_xr + (size_t)by * BM * CIN, CIN,
                  g_WT + (size_t)bx * BN * CIN, CIN, 0, CIN / BK, smem, acc, tid);

    const int lane = tid & 31, warp = tid >> 5;
    const int wm = warp >> 1, wn = warp & 1;
#pragma unroll
    for (int mt = 0; mt < 2; mt++) {
        const int r0 = by * BM + wm * 32 + mt * 16 + (lane >> 2);
#pragma unroll
        for (int nt = 0; nt < 8; nt++) {
            const int col = bx * BN + wn * 64 + nt * 8 + (lane & 3) * 2;
            const float b0 = bias[col], b1 = bias[col + 1];
            *(float2*)(g_qkv + (size_t)r0 * QKVN + col) =
                make_float2(rnd_tf32(acc[mt][nt][0] + b0), rnd_tf32(acc[mt][nt][1] + b1));
            *(float2*)(g_qkv + (size_t)(r0 + 8) * QKVN + col) =
                make_float2(rnd_tf32(acc[mt][nt][2] + b0), rnd_tf32(acc[mt][nt][3] + b1));
        }
    }
}

// ---------------------------------------------------------------------------
// GEMM 2: att = mask(q @ k^T * scale)  grid (32, 32)
// ---------------------------------------------------------------------------
__global__ __launch_bounds__(256, 2) void k_att_tc(const int* __restrict__ npadd_p) {
    extern __shared__ float smem[];
    const int tid = threadIdx.x;
    const int bx = blockIdx.x, by = blockIdx.y;
    if (bx > by) return;
    const int n_padd = *npadd_p;
    const int rowMax = by * BM + BM - 1;
    const int colMin = bx * BN, colMax = colMin + BN - 1;
    if (rowMax < n_padd) return;
    if (colMax < n_padd) {
        const float4 negv = make_float4(NEGV, NEGV, NEGV, NEGV);
        for (int i = tid; i < BM * BN / 4; i += 256) {
            int m = i >> 5, n = (i & 31) << 2;
            *(float4*)(g_att + (size_t)(by * BM + m) * TSEQ + colMin + n) = negv;
        }
        return;
    }

    float acc[2][8][4] = {};
    gemm_mainloop(g_qkv + (size_t)by * BM * QKVN, QKVN,
                  g_qkv + (size_t)bx * BN * QKVN + NF, QKVN, 0, NF / BK, smem, acc, tid);

    const float scale = 0.022097086912079608f;  // 1/sqrt(2048)
    const int lane = tid & 31, warp = tid >> 5;
    const int wm = warp >> 1, wn = warp & 1;
#pragma unroll
    for (int mt = 0; mt < 2; mt++) {
        const int r0 = by * BM + wm * 32 + mt * 16 + (lane >> 2);
        const int r1 = r0 + 8;
#pragma unroll
        for (int nt = 0; nt < 8; nt++) {
            const int col = bx * BN + wn * 64 + nt * 8 + (lane & 3) * 2;
            float2 o0, o1;
            o0.x = (r0 >= n_padd && col     <= r0 && col     >= n_padd) ? acc[mt][nt][0] * scale : NEGV;
            o0.y = (r0 >= n_padd && col + 1 <= r0 && col + 1 >= n_padd) ? acc[mt][nt][1] * scale : NEGV;
            o1.x = (r1 >= n_padd && col     <= r1 && col     >= n_padd) ? acc[mt][nt][2] * scale : NEGV;
            o1.y = (r1 >= n_padd && col + 1 <= r1 && col + 1 >= n_padd) ? acc[mt][nt][3] * scale : NEGV;
            *(float2*)(g_att + (size_t)r0 * TSEQ + col) = o0;
            *(float2*)(g_att + (size_t)r1 * TSEQ + col) = o1;
        }
    }
}

// ---------------------------------------------------------------------------
// GEMM 3: y = p @ vT^T   grid (16, 32); K in [n_padd&~31, (by+1)*128)
// ---------------------------------------------------------------------------
__global__ __launch_bounds__(256, 2) void k_out_tc(float* __restrict__ Y,
                                                   const int* __restrict__ npadd_p) {
    extern __shared__ float smem[];
    const int tid = threadIdx.x;
    const int bx = blockIdx.x, by = blockIdx.y;
    const int n_padd = *npadd_p;
    const int kStart = n_padd & ~(BK - 1);
    const int nk = ((by + 1) * BM - kStart) / BK;

    if (nk <= 0) {
        const float4 z = make_float4(0.f, 0.f, 0.f, 0.f);
        for (int i = tid; i < BM * BN / 4; i += 256) {
            int m = i >> 5, n = (i & 31) << 2;
            *(float4*)(Y + (size_t)(by * BM + m) * NF + bx * BN + n) = z;
        }
        return;
    }

    float acc[2][8][4] = {};
    gemm_mainloop(g_att + (size_t)by * BM * TSEQ, TSEQ,
                  g_vT + (size_t)bx * BN * TSEQ, TSEQ, kStart, nk, smem, acc, tid);

    const int lane = tid & 31, warp = tid >> 5;
    const int wm = warp >> 1, wn = warp & 1;
#pragma unroll
    for (int mt = 0; mt < 2; mt++) {
        const int r0 = by * BM + wm * 32 + mt * 16 + (lane >> 2);
#pragma unroll
        for (int nt = 0; nt < 8; nt++) {
            const int col = bx * BN + wn * 64 + nt * 8 + (lane & 3) * 2;
            *(float2*)(Y + (size_t)r0 * NF + col) =
                make_float2(acc[mt][nt][0], acc[mt][nt][1]);
            *(float2*)(Y + (size_t)(r0 + 8) * NF + col) =
                make_float2(acc[mt][nt][2], acc[mt][nt][3]);
        }
    }
}

// ---------------------------------------------------------------------------
// Transpose + round: dst[c][r] = tf32(src[r][c])
// ---------------------------------------------------------------------------
__global__ void k_transpose(const float* __restrict__ src, float* __restrict__ dst,
                            int lds, int ldd) {
    __shared__ float t[32][33];
    const int bx = blockIdx.x * 32, by = blockIdx.y * 32;
    const int x = threadIdx.x, y = threadIdx.y;
#pragma unroll
    for (int j = 0; j < 32; j += 8)
        t[y + j][x] = rnd_tf32(src[(size_t)(by + y + j) * lds + bx + x]);
    __syncthreads();
#pragma unroll
    for (int j = 0; j < 32; j += 8)
        dst[(size_t)(bx + y + j) * ldd + by + x] = t[x][y + j];
}

// Round-copy: g_xr = tf32(x)
__global__ void k_roundcpy(const float* __restrict__ src, float* __restrict__ dst, int n4) {
    int i = blockIdx.x * blockDim.x + threadIdx.x;
    if (i < n4) {
        float4 v = ((const float4*)src)[i];
        v.x = rnd_tf32(v.x); v.y = rnd_tf32(v.y);
        v.z = rnd_tf32(v.z); v.w = rnd_tf32(v.w);
        ((float4*)dst)[i] = v;
    }
}

// ---------------------------------------------------------------------------
// Row softmax: only the causal prefix [0, ceil128(r+1)) is read/written.
// Writes tf32-rounded probabilities. Padding rows -> zeros on the prefix.
// ---------------------------------------------------------------------------
__global__ __launch_bounds__(256) void k_softmax(const int* __restrict__ npadd_p) {
    const int r = blockIdx.x;
    const int n_padd = *npadd_p;
    const int cap = ((r >> 7) + 1) << 7;       // multiple of 128, > r
    float* row = g_att + (size_t)r * TSEQ;
    const int tid = threadIdx.x;
    if (r < n_padd) {
        for (int c = tid * 4; c < cap; c += 256 * 4)
            *(float4*)(row + c) = make_float4(0.f, 0.f, 0.f, 0.f);
        return;
    }
    __shared__ float redmax[8], redsum[8];
    float vals[16];
    float mx = NEGV;
#pragma unroll
    for (int i = 0; i < 16; i++) {
        const int c = tid + i * 256;
        vals[i] = (c < cap) ? row[c] : NEGV;
        mx = fmaxf(mx, vals[i]);
    }
#pragma unroll
    for (int o = 16; o > 0; o >>= 1) mx = fmaxf(mx, __shfl_xor_sync(0xffffffffu, mx, o));
    if ((tid & 31) == 0) redmax[tid >> 5] = mx;
    __syncthreads();
    mx = redmax[0];
#pragma unroll
    for (int i = 1; i < 8; i++) mx = fmaxf(mx, redmax[i]);
    float s = 0.f;
#pragma unroll
    for (int i = 0; i < 16; i++) {
        vals[i] = __expf(vals[i] - mx);    // underflows to 0 for masked entries
        s += vals[i];
    }
#pragma unroll
    for (int o = 16; o > 0; o >>= 1) s += __shfl_xor_sync(0xffffffffu, s, o);
    if ((tid & 31) == 0) redsum[tid >> 5] = s;
    __syncthreads();
    s = redsum[0];
#pragma unroll
    for (int i = 1; i < 8; i++) s += redsum[i];
    const float inv = 1.f / s;
#pragma unroll
    for (int i = 0; i < 16; i++) {
        const int c = tid + i * 256;
        if (c < cap) row[c] = rnd_tf32(vals[i] * inv);
    }
}

// ---------------------------------------------------------------------------
extern "C" void kernel_launch(void* const* d_in, const int* in_sizes, int n_in,
                              void* d_out, int out_size) {
    const float* x  = (const float*)d_in[0];
    const float* W  = (const float*)d_in[1];
    const float* b  = (const float*)d_in[2];
    const int* npad = (const int*)d_in[3];
    float* y = (float*)d_out;

    cudaFuncSetAttribute(k_qkv_tc, cudaFuncAttributeMaxDynamicSharedMemorySize, DYN_SMEM);
    cudaFuncSetAttribute(k_att_tc, cudaFuncAttributeMaxDynamicSharedMemorySize, DYN_SMEM);
    cudaFuncSetAttribute(k_out_tc, cudaFuncAttributeMaxDynamicSharedMemorySize, DYN_SMEM);

    float *wt_p, *vt_p, *qkv_p, *xr_p;
    cudaGetSymbolAddress((void**)&wt_p, g_WT);
    cudaGetSymbolAddress((void**)&vt_p, g_vT);
    cudaGetSymbolAddress((void**)&qkv_p, g_qkv);
    cudaGetSymbolAddress((void**)&xr_p, g_xr);

    dim3 tb(32, 8);
    const int nx4 = TSEQ * CIN / 4;
    k_roundcpy<<<(nx4 + 255) / 256, 256>>>(x, xr_p, nx4);
    // W (2048 x 6144) -> WT (6144 x 2048), rounded
    k_transpose<<<dim3(QKVN / 32, CIN / 32), tb>>>(W, wt_p, QKVN, CIN);
    k_qkv_tc<<<dim3(QKVN / BN, TSEQ / BM), 256, DYN_SMEM>>>(b, npad);
    // v = qkv[:, 2NF:] (4096 x 2048) -> vT (2048 x 4096)
    k_transpose<<<dim3(NF / 32, TSEQ / 32), tb>>>(qkv_p + 2 * NF, vt_p, QKVN, TSEQ);
    k_att_tc<<<dim3(TSEQ / BN, TSEQ / BM), 256, DYN_SMEM>>>(npad);
    k_softmax<<<TSEQ, 256>>>(npad);
    k_out_tc<<<dim3(NF / BN, TSEQ / BM), 256, DYN_SMEM>>>(y, npad);
}

// round 8
// speedup vs baseline: 4.3002x; 1.1092x over previous
#include <cuda_runtime.h>
#include <cstdint>

// Problem dims (fixed)
#define TSEQ 4096
#define CIN  2048
#define NF   2048
#define QKVN 6144
#define NEGV -1e30f

// GEMM tiling
#define BM 128
#define BN 128
#define BK 32
#define PADK 36                      // smem row stride (floats); 144B rows, 16B aligned
#define NSTAGE 3
#define TILE_FLOATS (BM * PADK)
#define TILE_BYTES  (TILE_FLOATS * 4)
#define BUF_FLOATS  (2 * TILE_FLOATS)              // A + B for one stage
#define BUF_BYTES   (BUF_FLOATS * 4)
#define DYN_SMEM    (NSTAGE * BUF_BYTES)           // 110592 B

// Scratch (device globals — allocation is forbidden; zero-initialized at load)
__device__ float g_qkv[(size_t)TSEQ * QKVN];   // 96 MB  [T][3*NF] (q|k|v), tf32-valued
__device__ float g_att[(size_t)TSEQ * TSEQ];   // 64 MB  att / probs
__device__ float g_WT [(size_t)QKVN * CIN];    // 48 MB  W^T, tf32-valued
__device__ float g_vT [(size_t)NF   * TSEQ];   // 32 MB  v^T, tf32-valued
__device__ float g_xr [(size_t)TSEQ * CIN];    // 32 MB  x rounded to tf32

// ---------------------------------------------------------------------------
// helpers
// ---------------------------------------------------------------------------
__device__ __forceinline__ uint32_t f2tf32(float f) {
    uint32_t u;
    asm("cvt.rna.tf32.f32 %0, %1;" : "=r"(u) : "f"(f));
    return u;
}
__device__ __forceinline__ float rnd_tf32(float f) { return __uint_as_float(f2tf32(f)); }

__device__ __forceinline__ uint32_t smem_u32(const void* p) {
    uint32_t a;
    asm("{ .reg .u64 t; cvta.to.shared.u64 t, %1; cvt.u32.u64 %0, t; }" : "=r"(a) : "l"(p));
    return a;
}

#define CP16(sa, gp) asm volatile("cp.async.cg.shared.global [%0], [%1], 16;" :: "r"(sa), "l"(gp))
#define CP_COMMIT()  asm volatile("cp.async.commit_group;" ::: "memory")
#define CP_WAIT(n)   asm volatile("cp.async.wait_group %0;" :: "n"(n) : "memory")

#define MMA_TF32(d, a0, a1, a2, a3, b0, b1) \
    asm volatile("mma.sync.aligned.m16n8k8.row.col.f32.tf32.tf32.f32 " \
        "{%0,%1,%2,%3}, {%4,%5,%6,%7}, {%8,%9}, {%0,%1,%2,%3};" \
        : "+f"((d)[0]), "+f"((d)[1]), "+f"((d)[2]), "+f"((d)[3]) \
        : "r"(a0), "r"(a1), "r"(a2), "r"(a3), "r"(b0), "r"(b1))

__device__ __forceinline__ void ldsm4(uint32_t* r, uint32_t addr) {
    asm volatile("ldmatrix.sync.aligned.m8n8.x4.shared.b16 {%0,%1,%2,%3}, [%4];"
                 : "=r"(r[0]), "=r"(r[1]), "=r"(r[2]), "=r"(r[3]) : "r"(addr));
}

// ---------------------------------------------------------------------------
// Stage one 128x32 fp32 tile (K-major) into smem via cp.async. 256 threads,
// 4 x 16B per thread.
// ---------------------------------------------------------------------------
__device__ __forceinline__ void stage_cp(const float* __restrict__ g, int ld, int k0,
                                         uint32_t sbase, int tid) {
#pragma unroll
    for (int j = 0; j < 4; j++) {
        const int idx = tid + 256 * j;
        const int r = idx >> 3, c = (idx & 7) << 2;
        CP16(sbase + (uint32_t)(r * PADK + c) * 4u, g + (size_t)r * ld + k0 + c);
    }
}

// ---------------------------------------------------------------------------
// Compute one K-chunk via ldmatrix fragment loads.
// aoff[mt]: lane-specific byte offset of A-fragment quadrant row (within tile)
// boff[ntp]: same for B fragment pairs (two nt tiles per ldsm.x4)
// ---------------------------------------------------------------------------
__device__ __forceinline__ void compute_chunk(uint32_t sA, uint32_t sB,
                                              const uint32_t aoff[2], const uint32_t boff[4],
                                              float acc[2][8][4]) {
#pragma unroll
    for (int kk = 0; kk < 4; kk++) {
        const uint32_t kb = (uint32_t)kk * 32u;      // 8 floats per kk
        uint32_t afr[2][4], bfr[4][4];
        ldsm4(afr[0], sA + aoff[0] + kb);
        ldsm4(afr[1], sA + aoff[1] + kb);
#pragma unroll
        for (int p = 0; p < 4; p++) ldsm4(bfr[p], sB + boff[p] + kb);
#pragma unroll
        for (int mt = 0; mt < 2; mt++)
#pragma unroll
            for (int nt = 0; nt < 8; nt++)
                MMA_TF32(acc[mt][nt],
                         afr[mt][0], afr[mt][1], afr[mt][2], afr[mt][3],
                         bfr[nt >> 1][(nt & 1) * 2], bfr[nt >> 1][(nt & 1) * 2 + 1]);
    }
}

// ---------------------------------------------------------------------------
// Mainloop: acc += A(128xK) @ B(128xK)^T over nk chunks of 32.
// 3-stage cp.async pipeline, one __syncthreads per chunk.
// ---------------------------------------------------------------------------
__device__ __forceinline__ void gemm_mainloop(const float* __restrict__ A, int lda,
                                              const float* __restrict__ B, int ldb,
                                              int kStart, int nk, float* smem,
                                              float acc[2][8][4], int tid) {
    const int lane = tid & 31, warp = tid >> 5;
    const int wm = warp >> 1, wn = warp & 1;
    const uint32_t s0 = smem_u32(smem);

    // ldmatrix lane address offsets (bytes, tile-relative)
    const int q = lane >> 3, qr = lane & 7;
    uint32_t aoff[2], boff[4];
#pragma unroll
    for (int mt = 0; mt < 2; mt++)
        aoff[mt] = (uint32_t)(((wm * 32 + mt * 16 + (q & 1) * 8 + qr) * PADK + (q >> 1) * 4) * 4);
#pragma unroll
    for (int p = 0; p < 4; p++)
        boff[p] = (uint32_t)(((wn * 64 + p * 16 + ((q >> 1) & 1) * 8 + qr) * PADK + (q & 1) * 4) * 4);

    // Prologue: fill NSTAGE-1 stages (pad with empty groups if nk is small)
#pragma unroll
    for (int s = 0; s < NSTAGE - 1; s++) {
        if (s < nk) {
            const uint32_t sb = s0 + (uint32_t)s * BUF_BYTES;
            stage_cp(A, lda, kStart + s * BK, sb, tid);
            stage_cp(B, ldb, kStart + s * BK, sb + TILE_BYTES, tid);
        }
        CP_COMMIT();
    }

    for (int i = 0; i < nk; i++) {
        CP_WAIT(NSTAGE - 2);          // buffer i%NSTAGE complete
        __syncthreads();              // all warps done reading buf (i-1)%NSTAGE
        if (i + NSTAGE - 1 < nk) {
            const int s = (i + NSTAGE - 1) % NSTAGE;
            const uint32_t sb = s0 + (uint32_t)s * BUF_BYTES;
            stage_cp(A, lda, kStart + (i + NSTAGE - 1) * BK, sb, tid);
            stage_cp(B, ldb, kStart + (i + NSTAGE - 1) * BK, sb + TILE_BYTES, tid);
        }
        CP_COMMIT();                  // (possibly empty) keeps in-flight uniform
        const uint32_t sA = s0 + (uint32_t)(i % NSTAGE) * BUF_BYTES;
        compute_chunk(sA, sA + TILE_BYTES, aoff, boff, acc);
    }
}

// Epilogue coords: row0 = wm*32+mt*16+(lane>>2), row1=row0+8;
//                  col = wn*64+nt*8+(lane&3)*2; acc = {d0,d1 @row0; d2,d3 @row1}

// ---------------------------------------------------------------------------
// GEMM 1: qkv = xr @ WT^T + b   grid (48, 32); skips all-padding row blocks
// ---------------------------------------------------------------------------
__global__ __launch_bounds__(256, 2) void k_qkv_tc(const float* __restrict__ bias,
                                                   const int* __restrict__ npadd_p) {
    extern __shared__ float smem[];
    const int tid = threadIdx.x;
    const int bx = blockIdx.x, by = blockIdx.y;
    if ((by + 1) * BM <= *npadd_p) return;
    float acc[2][8][4] = {};
    gemm_mainloop(g_xr + (size_t)by * BM * CIN, CIN,
                  g_WT + (size_t)bx * BN * CIN, CIN, 0, CIN / BK, smem, acc, tid);

    const int lane = tid & 31, warp = tid >> 5;
    const int wm = warp >> 1, wn = warp & 1;
#pragma unroll
    for (int mt = 0; mt < 2; mt++) {
        const int r0 = by * BM + wm * 32 + mt * 16 + (lane >> 2);
#pragma unroll
        for (int nt = 0; nt < 8; nt++) {
            const int col = bx * BN + wn * 64 + nt * 8 + (lane & 3) * 2;
            const float b0 = bias[col], b1 = bias[col + 1];
            *(float2*)(g_qkv + (size_t)r0 * QKVN + col) =
                make_float2(rnd_tf32(acc[mt][nt][0] + b0), rnd_tf32(acc[mt][nt][1] + b1));
            *(float2*)(g_qkv + (size_t)(r0 + 8) * QKVN + col) =
                make_float2(rnd_tf32(acc[mt][nt][2] + b0), rnd_tf32(acc[mt][nt][3] + b1));
        }
    }
}

// ---------------------------------------------------------------------------
// GEMM 2: att = mask(q @ k^T * scale)  grid (32, 32)
// ---------------------------------------------------------------------------
__global__ __launch_bounds__(256, 2) void k_att_tc(const int* __restrict__ npadd_p) {
    extern __shared__ float smem[];
    const int tid = threadIdx.x;
    const int bx = blockIdx.x, by = blockIdx.y;
    if (bx > by) return;
    const int n_padd = *npadd_p;
    const int rowMax = by * BM + BM - 1;
    const int colMin = bx * BN, colMax = colMin + BN - 1;
    if (rowMax < n_padd) return;
    if (colMax < n_padd) {
        const float4 negv = make_float4(NEGV, NEGV, NEGV, NEGV);
        for (int i = tid; i < BM * BN / 4; i += 256) {
            int m = i >> 5, n = (i & 31) << 2;
            *(float4*)(g_att + (size_t)(by * BM + m) * TSEQ + colMin + n) = negv;
        }
        return;
    }

    float acc[2][8][4] = {};
    gemm_mainloop(g_qkv + (size_t)by * BM * QKVN, QKVN,
                  g_qkv + (size_t)bx * BN * QKVN + NF, QKVN, 0, NF / BK, smem, acc, tid);

    const float scale = 0.022097086912079608f;  // 1/sqrt(2048)
    const int lane = tid & 31, warp = tid >> 5;
    const int wm = warp >> 1, wn = warp & 1;
#pragma unroll
    for (int mt = 0; mt < 2; mt++) {
        const int r0 = by * BM + wm * 32 + mt * 16 + (lane >> 2);
        const int r1 = r0 + 8;
#pragma unroll
        for (int nt = 0; nt < 8; nt++) {
            const int col = bx * BN + wn * 64 + nt * 8 + (lane & 3) * 2;
            float2 o0, o1;
            o0.x = (r0 >= n_padd && col     <= r0 && col     >= n_padd) ? acc[mt][nt][0] * scale : NEGV;
            o0.y = (r0 >= n_padd && col + 1 <= r0 && col + 1 >= n_padd) ? acc[mt][nt][1] * scale : NEGV;
            o1.x = (r1 >= n_padd && col     <= r1 && col     >= n_padd) ? acc[mt][nt][2] * scale : NEGV;
            o1.y = (r1 >= n_padd && col + 1 <= r1 && col + 1 >= n_padd) ? acc[mt][nt][3] * scale : NEGV;
            *(float2*)(g_att + (size_t)r0 * TSEQ + col) = o0;
            *(float2*)(g_att + (size_t)r1 * TSEQ + col) = o1;
        }
    }
}

// ---------------------------------------------------------------------------
// GEMM 3: y = p @ vT^T   grid (16, 32); K in [n_padd&~31, (by+1)*128)
// ---------------------------------------------------------------------------
__global__ __launch_bounds__(256, 2) void k_out_tc(float* __restrict__ Y,
                                                   const int* __restrict__ npadd_p) {
    extern __shared__ float smem[];
    const int tid = threadIdx.x;
    const int bx = blockIdx.x, by = blockIdx.y;
    const int n_padd = *npadd_p;
    const int kStart = n_padd & ~(BK - 1);
    const int nk = ((by + 1) * BM - kStart) / BK;

    if (nk <= 0) {
        const float4 z = make_float4(0.f, 0.f, 0.f, 0.f);
        for (int i = tid; i < BM * BN / 4; i += 256) {
            int m = i >> 5, n = (i & 31) << 2;
            *(float4*)(Y + (size_t)(by * BM + m) * NF + bx * BN + n) = z;
        }
        return;
    }

    float acc[2][8][4] = {};
    gemm_mainloop(g_att + (size_t)by * BM * TSEQ, TSEQ,
                  g_vT + (size_t)bx * BN * TSEQ, TSEQ, kStart, nk, smem, acc, tid);

    const int lane = tid & 31, warp = tid >> 5;
    const int wm = warp >> 1, wn = warp & 1;
#pragma unroll
    for (int mt = 0; mt < 2; mt++) {
        const int r0 = by * BM + wm * 32 + mt * 16 + (lane >> 2);
#pragma unroll
        for (int nt = 0; nt < 8; nt++) {
            const int col = bx * BN + wn * 64 + nt * 8 + (lane & 3) * 2;
            *(float2*)(Y + (size_t)r0 * NF + col) =
                make_float2(acc[mt][nt][0], acc[mt][nt][1]);
            *(float2*)(Y + (size_t)(r0 + 8) * NF + col) =
                make_float2(acc[mt][nt][2], acc[mt][nt][3]);
        }
    }
}

// ---------------------------------------------------------------------------
// Transpose + round: dst[c][r] = tf32(src[r][c])
// ---------------------------------------------------------------------------
__global__ void k_transpose(const float* __restrict__ src, float* __restrict__ dst,
                            int lds, int ldd) {
    __shared__ float t[32][33];
    const int bx = blockIdx.x * 32, by = blockIdx.y * 32;
    const int x = threadIdx.x, y = threadIdx.y;
#pragma unroll
    for (int j = 0; j < 32; j += 8)
        t[y + j][x] = rnd_tf32(src[(size_t)(by + y + j) * lds + bx + x]);
    __syncthreads();
#pragma unroll
    for (int j = 0; j < 32; j += 8)
        dst[(size_t)(bx + y + j) * ldd + by + x] = t[x][y + j];
}

// Round-copy: g_xr = tf32(x)
__global__ void k_roundcpy(const float* __restrict__ src, float* __restrict__ dst, int n4) {
    int i = blockIdx.x * blockDim.x + threadIdx.x;
    if (i < n4) {
        float4 v = ((const float4*)src)[i];
        v.x = rnd_tf32(v.x); v.y = rnd_tf32(v.y);
        v.z = rnd_tf32(v.z); v.w = rnd_tf32(v.w);
        ((float4*)dst)[i] = v;
    }
}

// ---------------------------------------------------------------------------
// Row softmax: only the causal prefix [0, ceil128(r+1)) is read/written.
// ---------------------------------------------------------------------------
__global__ __launch_bounds__(256) void k_softmax(const int* __restrict__ npadd_p) {
    const int r = blockIdx.x;
    const int n_padd = *npadd_p;
    const int cap = ((r >> 7) + 1) << 7;       // multiple of 128, > r
    float* row = g_att + (size_t)r * TSEQ;
    const int tid = threadIdx.x;
    if (r < n_padd) {
        for (int c = tid * 4; c < cap; c += 256 * 4)
            *(float4*)(row + c) = make_float4(0.f, 0.f, 0.f, 0.f);
        return;
    }
    __shared__ float redmax[8], redsum[8];
    float vals[16];
    float mx = NEGV;
#pragma unroll
    for (int i = 0; i < 16; i++) {
        const int c = tid + i * 256;
        vals[i] = (c < cap) ? row[c] : NEGV;
        mx = fmaxf(mx, vals[i]);
    }
#pragma unroll
    for (int o = 16; o > 0; o >>= 1) mx = fmaxf(mx, __shfl_xor_sync(0xffffffffu, mx, o));
    if ((tid & 31) == 0) redmax[tid >> 5] = mx;
    __syncthreads();
    mx = redmax[0];
#pragma unroll
    for (int i = 1; i < 8; i++) mx = fmaxf(mx, redmax[i]);
    float s = 0.f;
#pragma unroll
    for (int i = 0; i < 16; i++) {
        vals[i] = __expf(vals[i] - mx);    // underflows to 0 for masked entries
        s += vals[i];
    }
#pragma unroll
    for (int o = 16; o > 0; o >>= 1) s += __shfl_xor_sync(0xffffffffu, s, o);
    if ((tid & 31) == 0) redsum[tid >> 5] = s;
    __syncthreads();
    s = redsum[0];
#pragma unroll
    for (int i = 1; i < 8; i++) s += redsum[i];
    const float inv = 1.f / s;
#pragma unroll
    for (int i = 0; i < 16; i++) {
        const int c = tid + i * 256;
        if (c < cap) row[c] = rnd_tf32(vals[i] * inv);
    }
}

// ---------------------------------------------------------------------------
extern "C" void kernel_launch(void* const* d_in, const int* in_sizes, int n_in,
                              void* d_out, int out_size) {
    const float* x  = (const float*)d_in[0];
    const float* W  = (const float*)d_in[1];
    const float* b  = (const float*)d_in[2];
    const int* npad = (const int*)d_in[3];
    float* y = (float*)d_out;

    cudaFuncSetAttribute(k_qkv_tc, cudaFuncAttributeMaxDynamicSharedMemorySize, DYN_SMEM);
    cudaFuncSetAttribute(k_att_tc, cudaFuncAttributeMaxDynamicSharedMemorySize, DYN_SMEM);
    cudaFuncSetAttribute(k_out_tc, cudaFuncAttributeMaxDynamicSharedMemorySize, DYN_SMEM);

    float *wt_p, *vt_p, *qkv_p, *xr_p;
    cudaGetSymbolAddress((void**)&wt_p, g_WT);
    cudaGetSymbolAddress((void**)&vt_p, g_vT);
    cudaGetSymbolAddress((void**)&qkv_p, g_qkv);
    cudaGetSymbolAddress((void**)&xr_p, g_xr);

    dim3 tb(32, 8);
    const int nx4 = TSEQ * CIN / 4;
    k_roundcpy<<<(nx4 + 255) / 256, 256>>>(x, xr_p, nx4);
    // W (2048 x 6144) -> WT (6144 x 2048), rounded
    k_transpose<<<dim3(QKVN / 32, CIN / 32), tb>>>(W, wt_p, QKVN, CIN);
    k_qkv_tc<<<dim3(QKVN / BN, TSEQ / BM), 256, DYN_SMEM>>>(b, npad);
    // v = qkv[:, 2NF:] (4096 x 2048) -> vT (2048 x 4096)
    k_transpose<<<dim3(NF / 32, TSEQ / 32), tb>>>(qkv_p + 2 * NF, vt_p, QKVN, TSEQ);
    k_att_tc<<<dim3(TSEQ / BN, TSEQ / BM), 256, DYN_SMEM>>>(npad);
    k_softmax<<<TSEQ, 256>>>(npad);
    k_out_tc<<<dim3(NF / BN, TSEQ / BM), 256, DYN_SMEM>>>(y, npad);
}